// round 17
// baseline (speedup 1.0000x reference)
#include <cuda_runtime.h>
#include <stdint.h>

#define D 128
#define K 16
#define TPB 128
#define WARPS 4
#define WROWS 16                // rows per warp unit
#define CH 32                   // columns per chunk (128B/row)
#define NCH 4                   // chunks per unit
#define ROWSTRIDE 144           // 128B data + 16B pad (LDS.32 frag loads conflict-free)
#define STAGE_BYTES (WROWS * ROWSTRIDE)      // 2304
#define NSTAGE 4
#define WARP_STAGING (NSTAGE * STAGE_BYTES)  // 9216
#define ASTRIDE 132             // floats per A row in smem (bank 4n+c, conflict-free)
#define SM_AH 0                 // A_hi: 16*528 = 8448
#define SM_CU 8448              // c (16f) + U (16f)
#define SMEM_HDR 8576
#define SMEM_TOTAL (SMEM_HDR + WARPS * WARP_STAGING)   // 45440 -> 5 CTAs/SM (proven R15)
#define NBLK 740                // persistent: 148 SMs x 5 CTAs

__device__ float gA[K * D];     // A row-major [k][d] (full fp32)
__device__ float gC[K];
__device__ unsigned int gCtr;   // work-stealing unit counter (reset by prep)

// ---------------- helpers ----------------
__device__ __forceinline__ void cp_async16(uint32_t dst, const void* src, int src_bytes) {
    asm volatile("cp.async.cg.shared.global [%0], [%1], 16, %2;\n"
                 :: "r"(dst), "l"(src), "r"(src_bytes));
}
__device__ __forceinline__ void cp_commit() {
    asm volatile("cp.async.commit_group;\n" ::: "memory");
}
__device__ __forceinline__ void cp_wait3() {
    asm volatile("cp.async.wait_group 3;\n" ::: "memory");
}
__device__ __forceinline__ uint32_t lds32(uint32_t addr) {
    uint32_t v;
    asm volatile("ld.shared.b32 %0, [%1];" : "=r"(v) : "r"(addr));
    return v;
}
// D += A(16x8 tf32, row) @ B(8x8 tf32, col)
__device__ __forceinline__ void mma_tf32(float* c,
                                         uint32_t a0, uint32_t a1, uint32_t a2, uint32_t a3,
                                         uint32_t b0, uint32_t b1) {
    asm volatile(
        "mma.sync.aligned.m16n8k8.row.col.f32.tf32.tf32.f32 "
        "{%0,%1,%2,%3}, {%4,%5,%6,%7}, {%8,%9}, {%0,%1,%2,%3};"
        : "+f"(c[0]), "+f"(c[1]), "+f"(c[2]), "+f"(c[3])
        : "r"(a0), "r"(a1), "r"(a2), "r"(a3), "r"(b0), "r"(b1));
}

// ---------------- merged prep (single launch) ----------------
__global__ void ntn_prep(const float* __restrict__ x2,
                         const float* __restrict__ V,
                         const float* __restrict__ W,
                         const float* __restrict__ b) {
    const int lane = threadIdx.x & 31;
    const int wid = threadIdx.x >> 5;
    const float4 x4 = ((const float4*)x2)[lane];

    if (blockIdx.x < 128) {
        const int gw = blockIdx.x * 4 + wid;        // 0..511, rows 4gw..4gw+3
        float4 w4[4];
#pragma unroll
        for (int rr = 0; rr < 4; rr++)
            w4[rr] = ((const float4*)(W + (size_t)(gw * 4 + rr) * D))[lane];
        float dots[4];
#pragma unroll
        for (int rr = 0; rr < 4; rr++)
            dots[rr] = w4[rr].x * x4.x + w4[rr].y * x4.y + w4[rr].z * x4.z + w4[rr].w * x4.w;
#pragma unroll
        for (int s = 16; s > 0; s >>= 1) {
#pragma unroll
            for (int rr = 0; rr < 4; rr++)
                dots[rr] += __shfl_xor_sync(0xffffffffu, dots[rr], s);
        }
        if (lane == 0) {
#pragma unroll
            for (int rr = 0; rr < 4; rr++) {
                const int row = gw * 4 + rr;        // = k*128 + d
                const int k = row >> 7;
                gA[row] = V[(size_t)k * 2 * D + (row & (D - 1))] + dots[rr];
            }
        }
    } else {
        if (threadIdx.x == 0) gCtr = 0u;
#pragma unroll
        for (int kk = 0; kk < 4; kk++) {
            const int k = wid * 4 + kk;
            const float4 v4 = ((const float4*)(V + (size_t)k * 2 * D + D))[lane];
            float dot = v4.x * x4.x + v4.y * x4.y + v4.z * x4.z + v4.w * x4.w;
#pragma unroll
            for (int s = 16; s > 0; s >>= 1)
                dot += __shfl_xor_sync(0xffffffffu, dot, s);
            if (lane == 0) gC[k] = dot + b[k];
        }
    }
}

// ---------------- main: mma.sync tf32, 4-stage pipeline, work-stealing 16-row units ----------------
__global__ __launch_bounds__(TPB, 5)
void ntn_main(const float* __restrict__ x1,
              const float* __restrict__ U,
              float* __restrict__ out, int n, int nunits) {
    extern __shared__ __align__(16) char sm[];
    float* sC = (float*)(sm + SM_CU);
    float* sU = sC + K;

    const int tid = threadIdx.x;
    const int wid = tid >> 5;
    const int lane = tid & 31;
    const int lq = lane >> 2;        // fragment row group 0..7
    const int lr = lane & 3;         // fragment col group 0..3

    const uint32_t smb = (uint32_t)__cvta_generic_to_shared(sm);
    const uint32_t sAh_u = smb + SM_AH;
    const uint32_t wstage = smb + SMEM_HDR + (uint32_t)wid * WARP_STAGING;

    // grab a unit (warp-uniform)
    auto grab = [&]() -> int {
        unsigned int v;
        if (lane == 0) v = atomicAdd(&gCtr, 1u);
        return (int)__shfl_sync(0xffffffffu, v, 0);
    };

    // per-warp chunk issue: 16 rows x 32 cols (128B/row) -> 4 cp.async16 per lane
    auto issue = [&](int unit, int ch, int buf) {
        const uint32_t base = wstage + (uint32_t)buf * STAGE_BYTES;
        const int rowbase = unit * WROWS;
#pragma unroll
        for (int i = 0; i < 4; i++) {
            const int idx = i * 32 + lane;
            const int r = idx >> 3;          // 0..15
            const int c = idx & 7;           // float4 within 128B row-chunk
            const int grow = rowbase + r;
            const int ok = (grow < n);
            const float* src = x1 + (size_t)(ok ? grow : 0) * D + ch * CH + c * 4;
            cp_async16(base + (uint32_t)(r * ROWSTRIDE + c * 16), src, ok ? 16 : 0);
        }
    };

    // issue cursor state
    int u = grab();          // current compute unit
    int iu = u;              // unit being issued
    int ic = 0;              // next chunk index to issue within iu
    int unext = -1;          // successor compute unit (set when cursor wraps)
    int ibuf = 0;            // next stage buffer to fill

    auto issue_advance = [&]() {
        if (ic == NCH) { iu = grab(); unext = iu; ic = 0; }
        if (iu < nunits) issue(iu, ic, ibuf);
        ic++;
        ibuf = (ibuf + 1) & (NSTAGE - 1);
        cp_commit();
    };

    // prologue: 3 chunks in flight before header load
    issue_advance(); issue_advance(); issue_advance();

    // header: A_hi (RN-rounded tf32) into padded smem, c, U (single block barrier)
    for (int i = tid; i < K * D; i += TPB) {
        const int k = i >> 7, d = i & (D - 1);
        float h;
        asm("cvt.rna.tf32.f32 %0, %1;" : "=f"(h) : "f"(gA[i]));
        ((float*)sm)[k * ASTRIDE + d] = h;
    }
    if (tid < K) { sC[tid] = gC[tid]; sU[tid] = U[tid]; }
    __syncthreads();

    int cbuf = 0;   // stage buffer of the chunk being consumed
    while (u < nunits) {
        float acc[2][4];   // [n-tile t][frag]
#pragma unroll
        for (int t = 0; t < 2; t++)
#pragma unroll
            for (int j = 0; j < 4; j++) acc[t][j] = 0.f;

#pragma unroll
        for (int ch = 0; ch < NCH; ch++) {
            issue_advance();            // keeps 3 chunks in flight (wraps into next unit)
            cp_wait3();                 // <=3 pending => chunk (u,ch) landed
            __syncwarp();

            const uint32_t wb = wstage + (uint32_t)cbuf * STAGE_BYTES;
#pragma unroll
            for (int ks = 0; ks < 4; ks++) {           // 4 k-steps of 8 within 32-col chunk
                const int kg = ch * CH + ks * 8;       // global k (D-dim) of this step
                uint32_t bh[2][2];
#pragma unroll
                for (int t = 0; t < 2; t++) {
                    const uint32_t ab = (uint32_t)(((t * 8 + lq) * ASTRIDE + kg + lr) * 4);
                    bh[t][0] = lds32(sAh_u + ab);
                    bh[t][1] = lds32(sAh_u + ab + 16);
                }
                // x fragment: rows {lq, lq+8}, cols {lr, lr+4} of this 8-k step
                const uint32_t xb = wb + (uint32_t)(lq * ROWSTRIDE + (ks * 8 + lr) * 4);
                const uint32_t x0 = lds32(xb);
                const uint32_t x1r = lds32(xb + 8 * ROWSTRIDE);
                const uint32_t x2r = lds32(xb + 16);
                const uint32_t x3r = lds32(xb + 8 * ROWSTRIDE + 16);
                const uint32_t h0 = x0 & 0xFFFFE000u, h1 = x1r & 0xFFFFE000u;
                const uint32_t h2 = x2r & 0xFFFFE000u, h3 = x3r & 0xFFFFE000u;
                const uint32_t l0 = __float_as_uint(__uint_as_float(x0) - __uint_as_float(h0));
                const uint32_t l1 = __float_as_uint(__uint_as_float(x1r) - __uint_as_float(h1));
                const uint32_t l2 = __float_as_uint(__uint_as_float(x2r) - __uint_as_float(h2));
                const uint32_t l3 = __float_as_uint(__uint_as_float(x3r) - __uint_as_float(h3));
#pragma unroll
                for (int t = 0; t < 2; t++) {
                    mma_tf32(acc[t], h0, h1, h2, h3, bh[t][0], bh[t][1]);  // xh @ Ah
                    mma_tf32(acc[t], l0, l1, l2, l3, bh[t][0], bh[t][1]);  // xl @ Ah
                }
            }
            __syncwarp();   // WAR before buf re-issue
            cbuf = (cbuf + 1) & (NSTAGE - 1);
        }

        // epilogue: thread holds D[row][k] for rows {lq, lq+8}, k = t*8 + 2*lr + {0,1}
#pragma unroll
        for (int hh = 0; hh < 2; hh++) {
            float part = 0.f;
#pragma unroll
            for (int t = 0; t < 2; t++) {
#pragma unroll
                for (int e = 0; e < 2; e++) {
                    const int k = t * 8 + 2 * lr + e;
                    const float v = acc[t][hh * 2 + e] + sC[k];
                    part = fmaf(fmaxf(v, 0.f), sU[k], part);
                }
            }
            part += __shfl_xor_sync(0xffffffffu, part, 1);
            part += __shfl_xor_sync(0xffffffffu, part, 2);
            const int row = u * WROWS + hh * 8 + lq;
            if (lr == 0 && row < n) out[row] = part;
        }

        u = unext;   // successor unit (its chunks are already streaming)
    }
    asm volatile("cp.async.wait_all;\n" ::: "memory");
}

// ---------------- launch ----------------
extern "C" void kernel_launch(void* const* d_in, const int* in_sizes, int n_in,
                              void* d_out, int out_size) {
    const float* x1 = nullptr; const float* x2 = nullptr; const float* V = nullptr;
    const float* W = nullptr;  const float* b = nullptr;  const float* U = nullptr;
    int n16 = 0;
    for (int i = 0; i < n_in; i++) {
        const int s = in_sizes[i];
        const float* p = (const float*)d_in[i];
        if (s == 128) x2 = p;
        else if (s == 4096) V = p;
        else if (s == 262144) W = p;
        else if (s == 16) { if (n16++ == 0) b = p; else U = p; }
        else x1 = p;
    }
    int n = 0;
    for (int i = 0; i < n_in; i++) if ((const float*)d_in[i] == x1) n = in_sizes[i] / D;

    float* out = (float*)d_out;

    ntn_prep<<<129, TPB>>>(x2, V, W, b);

    const int nunits = (n + WROWS - 1) / WROWS;
    int blocks = (nunits + WARPS - 1) / WARPS;
    if (blocks > NBLK) blocks = NBLK;
    cudaFuncSetAttribute(ntn_main, cudaFuncAttributeMaxDynamicSharedMemorySize, SMEM_TOTAL);
    ntn_main<<<blocks, TPB, SMEM_TOTAL>>>(x1, U, out, n, nunits);
}